// round 4
// baseline (speedup 1.0000x reference)
#include <cuda_runtime.h>

// Problem constants
#define Bn  16
#define Cn  32
#define Nn  128
#define Tn  12
#define COn 64
#define NT  (Nn * Tn)          // 1536 floats per (b,i,j) row of A
#define NT4 (NT / 4)           // 384 float4
#define NSLICE (Bn * Cn)       // 512 (b,i) slices

// prop config: 128 persistent CTAs (1/SM via smem pad), 768 threads =
// 4 groups x 192; each group streams 32 of the 128 j-rows.
#define PROP_CTAS    128
#define PROP_THREADS 768
#define NGRP 4
#define GSZ  192
#define JPG  (Nn / NGRP)          // 32
#define SLICES_PER_CTA (NSLICE / PROP_CTAS)   // 4
#define PROP_PAD (150 * 1024)     // 60KB static + 150KB pad -> 1 CTA/SM

// Scratch: h = concat([x1, x2], channel axis) -> [B][2C][N*T] = 6.3 MB
__device__ float g_h[(size_t)Bn * 2 * Cn * NT];

extern __shared__ char s_pad[];   // occupancy limiter (never accessed)

__device__ __forceinline__ void fma4(float4& acc, const float4 a, const float4 v) {
    acc.x = fmaf(a.x, v.x, acc.x);
    acc.y = fmaf(a.y, v.y, acc.y);
    acc.z = fmaf(a.z, v.z, acc.z);
    acc.w = fmaf(a.w, v.w, acc.w);
}
__device__ __forceinline__ float4 add4(const float4 a, const float4 b) {
    return make_float4(a.x + b.x, a.y + b.y, a.z + b.z, a.w + b.w);
}
__device__ __forceinline__ float4 zero4() { return make_float4(0.f, 0.f, 0.f, 0.f); }

// ---------------------------------------------------------------------------
// Kernel 1: fused order-1 + order-2 propagation, software-pipelined across
// slices. In the steady state each fused loop iteration streams:
//   - pass 2 of slice s from L2 (last-use loads; lines die as read)
//   - pass 1 of slice s+128 from HBM (fills L2 for its own pass 2)
// so HBM streaming and L2 re-reads overlap instead of alternating.
// ---------------------------------------------------------------------------
__global__ __launch_bounds__(PROP_THREADS, 1)
void prop_kernel(const float* __restrict__ x, const float* __restrict__ A) {
    __shared__ float4 partA[NGRP][NT4];  // pass-1 partials (next slice)   24 KB
    __shared__ float4 partB[NGRP][NT4];  // pass-2 partials (current slice)24 KB
    __shared__ float4 xs[NT4];           // x slice (next),  [j*3 + lq]     6 KB
    __shared__ float4 x1s[NT4];          // x1 slice (current)              6 KB

    const int t  = threadIdx.x;
    const int g  = t / GSZ;
    const int ti = t - g * GSZ;          // 0..191
    const int lq = ti % 3;
    const int j0 = g * JPG;
    const int bc0 = blockIdx.x;

    // ---- Prologue: pass 1 of first slice
    if (t < NT4) xs[t] = ((const float4*)(x + (size_t)bc0 * NT))[t];
    __syncthreads();
    {
        const float4* __restrict__ ap =
            (const float4*)(A + (size_t)bc0 * Nn * NT) + (size_t)j0 * NT4;
        float4 a0 = zero4(), a1 = zero4();
#pragma unroll 4
        for (int jj = 0; jj < JPG; ++jj) {
            float4 n0 = ap[jj * NT4 + ti];
            float4 n1 = ap[jj * NT4 + ti + GSZ];
            float4 xv = xs[(j0 + jj) * 3 + lq];
            fma4(a0, n0, xv);
            fma4(a1, n1, xv);
        }
        partA[g][ti]       = a0;
        partA[g][ti + GSZ] = a1;
    }
    __syncthreads();
    float4 r1 = zero4();
    if (t < NT4) {
        r1 = add4(add4(partA[0][t], partA[1][t]), add4(partA[2][t], partA[3][t]));
        x1s[t] = r1;
    }

    // ---- Steady state
    for (int it = 0; it < SLICES_PER_CTA; ++it) {
        const int s         = bc0 + it * PROP_CTAS;
        const bool has_next = (it + 1 < SLICES_PER_CTA);
        const int snext     = s + PROP_CTAS;

        if (has_next && t < NT4)
            xs[t] = ((const float4*)(x + (size_t)snext * NT))[t];
        __syncthreads();   // xs & x1s ready; partA/partB free (prev reduce done)

        const float4* __restrict__ apc =
            (const float4*)(A + (size_t)s * Nn * NT) + (size_t)j0 * NT4;
        float4 b0 = zero4(), b1 = zero4();

        if (has_next) {
            const float4* __restrict__ apn =
                (const float4*)(A + (size_t)snext * Nn * NT) + (size_t)j0 * NT4;
            float4 a0 = zero4(), a1 = zero4();
#pragma unroll 2
            for (int jj = 0; jj < JPG; ++jj) {
                float4 c0 = __ldlu(&apc[jj * NT4 + ti]);          // pass 2 (L2, last-use)
                float4 c1 = __ldlu(&apc[jj * NT4 + ti + GSZ]);
                float4 n0 = apn[jj * NT4 + ti];                   // pass 1 (HBM, fill L2)
                float4 n1 = apn[jj * NT4 + ti + GSZ];
                float4 xv1 = x1s[(j0 + jj) * 3 + lq];
                float4 xv0 = xs[(j0 + jj) * 3 + lq];
                fma4(b0, c0, xv1);
                fma4(b1, c1, xv1);
                fma4(a0, n0, xv0);
                fma4(a1, n1, xv0);
            }
            partA[g][ti]       = a0;
            partA[g][ti + GSZ] = a1;
        } else {
#pragma unroll 4
            for (int jj = 0; jj < JPG; ++jj) {
                float4 c0 = __ldlu(&apc[jj * NT4 + ti]);
                float4 c1 = __ldlu(&apc[jj * NT4 + ti + GSZ]);
                float4 xv1 = x1s[(j0 + jj) * 3 + lq];
                fma4(b0, c0, xv1);
                fma4(b1, c1, xv1);
            }
        }
        partB[g][ti]       = b0;
        partB[g][ti + GSZ] = b1;
        __syncthreads();   // partials ready

        if (t < NT4) {
            float4 r2 = add4(add4(partB[0][t], partB[1][t]), add4(partB[2][t], partB[3][t]));
            const int b = s / Cn;
            const int i = s % Cn;
            ((float4*)(g_h + ((size_t)b * 2 * Cn + i) * NT))[t]      = r1;
            ((float4*)(g_h + ((size_t)b * 2 * Cn + Cn + i) * NT))[t] = r2;
            if (has_next) {
                r1 = add4(add4(partA[0][t], partA[1][t]), add4(partA[2][t], partA[3][t]));
                x1s[t] = r1;
            }
        }
        // loop-top __syncthreads() orders these writes vs. next fused loop
    }
}

// ---------------------------------------------------------------------------
// Kernel 2: 1x1 conv channel mix, smem-tiled GEMM. 32-col tiles -> 768 blocks
// (~5.2 CTAs/SM) to fix the grid-limited occupancy seen at 64-col tiles.
// Thread (oq=t/8, colq=t%8) computes 2 outs x 8 cols (2 float4 accs).
// ---------------------------------------------------------------------------
#define MIX_COLS 32
#define MIX_NCB  (NT / MIX_COLS)   // 48

__global__ __launch_bounds__(256) void mix_kernel(const float* __restrict__ W,
                                                  const float* __restrict__ bias,
                                                  float* __restrict__ out) {
    __shared__ float4 hs[(2 * Cn) * (MIX_COLS / 4)];   // 64ch x 8 f4 = 8 KB
    __shared__ float  Ws[COn * 2 * Cn];                // 16 KB
    __shared__ float  bs[COn];

    const int t    = threadIdx.x;
    const int b    = blockIdx.x / MIX_NCB;
    const int col0 = (blockIdx.x % MIX_NCB) * MIX_COLS;
    const int colq = t & 7;        // float4 column within tile
    const int oq   = t >> 3;       // 0..31, owns outs {2oq, 2oq+1}

    {
        float4*       Wd = (float4*)Ws;
        const float4* W4 = (const float4*)W;
#pragma unroll
        for (int s = 0; s < 4; ++s) Wd[t + 256 * s] = W4[t + 256 * s];
        if (t < COn) bs[t] = bias[t];
    }
    {
        const float* hb = g_h + (size_t)b * 2 * Cn * NT + col0;
#pragma unroll
        for (int s = 0; s < 2; ++s) {
            int idx = t + 256 * s;             // 0..511
            int c   = idx >> 3;
            int v   = idx & 7;
            hs[idx] = ((const float4*)(hb + (size_t)c * NT))[v];
        }
    }
    __syncthreads();

    const int o0 = 2 * oq, o1 = 2 * oq + 1;
    float4 acc0 = make_float4(bs[o0], bs[o0], bs[o0], bs[o0]);
    float4 acc1 = make_float4(bs[o1], bs[o1], bs[o1], bs[o1]);

#pragma unroll 16
    for (int c = 0; c < 2 * Cn; ++c) {
        float4 hv = hs[c * 8 + colq];
        float  w0 = Ws[o0 * 2 * Cn + c];
        float  w1 = Ws[o1 * 2 * Cn + c];
        acc0.x = fmaf(w0, hv.x, acc0.x); acc0.y = fmaf(w0, hv.y, acc0.y);
        acc0.z = fmaf(w0, hv.z, acc0.z); acc0.w = fmaf(w0, hv.w, acc0.w);
        acc1.x = fmaf(w1, hv.x, acc1.x); acc1.y = fmaf(w1, hv.y, acc1.y);
        acc1.z = fmaf(w1, hv.z, acc1.z); acc1.w = fmaf(w1, hv.w, acc1.w);
    }

    float* ob = out + (size_t)b * COn * NT + col0;
    ((float4*)(ob + (size_t)o0 * NT))[colq] = acc0;
    ((float4*)(ob + (size_t)o1 * NT))[colq] = acc1;
}

// ---------------------------------------------------------------------------
extern "C" void kernel_launch(void* const* d_in, const int* in_sizes, int n_in,
                              void* d_out, int out_size) {
    const float* x    = (const float*)d_in[0];   // [B,C,N,T]
    const float* A    = (const float*)d_in[1];   // [B,C,N,N,T]
    const float* W    = (const float*)d_in[2];   // [C_OUT, 2C]
    const float* bias = (const float*)d_in[3];   // [C_OUT]
    float* out = (float*)d_out;                  // [B,C_OUT,N,T]

    cudaFuncSetAttribute(prop_kernel, cudaFuncAttributeMaxDynamicSharedMemorySize, PROP_PAD);

    prop_kernel<<<PROP_CTAS, PROP_THREADS, PROP_PAD>>>(x, A);
    mix_kernel<<<Bn * MIX_NCB, 256>>>(W, bias, out);
}

// round 5
// speedup vs baseline: 1.2385x; 1.2385x over previous
#include <cuda_runtime.h>
#include <cooperative_groups.h>

namespace cg = cooperative_groups;

// Problem constants
#define Bn  16
#define Cn  32
#define Nn  128
#define Tn  12
#define COn 64
#define NT  (Nn * Tn)          // 1536 floats per (b,i,j) row of A
#define NT4 (NT / 4)           // 384 float4
#define NSLICE (Bn * Cn)       // 512 (b,i) slices

// prop: 64 clusters x 2 CTAs. Cluster handles one slice at a time; CTA rank r
// owns the k-half -> per-CTA per-slice A footprint 393 KB.
#define NPAIR 64
#define PROP_CTAS (2 * NPAIR)          // 128
#define PROP_THREADS 768
#define NGRP 4
#define GSZ  192
#define JPG  (Nn / NGRP)               // 32
#define HALF4 192                      // float4 per j-row half (768 floats)
#define SPP  (NSLICE / NPAIR)          // 8 slices per cluster
#define PROP_PAD (150 * 1024)          // 39KB static + 150KB pad -> 1 CTA/SM

// Scratch: h = concat([x1, x2], channel axis) -> [B][2C][N*T] = 6.3 MB
__device__ float g_h[(size_t)Bn * 2 * Cn * NT];

extern __shared__ char s_pad[];   // occupancy limiter (never accessed)

__device__ __forceinline__ void fma4(float4& acc, const float4 a, const float4 v) {
    acc.x = fmaf(a.x, v.x, acc.x);
    acc.y = fmaf(a.y, v.y, acc.y);
    acc.z = fmaf(a.z, v.z, acc.z);
    acc.w = fmaf(a.w, v.w, acc.w);
}
__device__ __forceinline__ float4 add4(const float4 a, const float4 b) {
    return make_float4(a.x + b.x, a.y + b.y, a.z + b.z, a.w + b.w);
}
__device__ __forceinline__ float4 zero4() { return make_float4(0.f, 0.f, 0.f, 0.f); }

// ---------------------------------------------------------------------------
// Kernel 1: fused order-1/order-2 propagation. 2-CTA clusters split each
// slice's k-range. Steady-state fused loop streams pass-2 of slice s from L2
// (last-use) concurrently with pass-1 of slice s+64 from HBM. x1 halves are
// exchanged via DSMEM each iteration.
// ---------------------------------------------------------------------------
__global__ __launch_bounds__(PROP_THREADS, 1) __cluster_dims__(2, 1, 1)
void prop_kernel(const float* __restrict__ x, const float* __restrict__ A) {
    __shared__ float4 partA[NGRP][HALF4];  // pass-1 partials (next slice)  12 KB
    __shared__ float4 partB[NGRP][HALF4];  // pass-2 partials (curr slice)  12 KB
    __shared__ float4 xs[NT4];             // x of next slice (full)         6 KB
    __shared__ float4 x1f[NT4];            // full x1 of current slice       6 KB
    __shared__ float4 x1mine[HALF4];       // my x1 half (DSMEM exchange)    3 KB

    cg::cluster_group cluster = cg::this_cluster();

    const int t  = threadIdx.x;
    const int g  = t / GSZ;
    const int ti = t - g * GSZ;            // 0..191 = float4 position in half
    const int lq = ti % 3;
    const int j0 = g * JPG;
    const int r  = (int)cluster.block_rank();   // 0/1 = k-half
    const int q  = blockIdx.x >> 1;             // pair index 0..63

    const float4* __restrict__ x4 = (const float4*)x;
    const float4* __restrict__ A4 = (const float4*)A;
    const float4* peer_x1 = cluster.map_shared_rank((const float4*)x1mine, 1 - r);

    // ---- Prologue: pass 1 of first slice (s0 = q), half-k
    {
        const int s0 = q;
        if (t < NT4) xs[t] = x4[(size_t)s0 * NT4 + t];
        __syncthreads();
        const float4* __restrict__ ap =
            A4 + ((size_t)s0 * Nn + j0) * NT4 + r * HALF4;
        float4 a0 = zero4();
#pragma unroll 4
        for (int jj = 0; jj < JPG; ++jj)
            fma4(a0, ap[(size_t)jj * NT4 + ti], xs[(j0 + jj) * 3 + lq]);
        partA[g][ti] = a0;
        __syncthreads();
        if (t < HALF4) {
            float4 r1 = add4(add4(partA[0][t], partA[1][t]),
                             add4(partA[2][t], partA[3][t]));
            x1mine[t]            = r1;
            x1f[r * HALF4 + t]   = r1;
        }
        cluster.sync();                         // publish x1mine
        if (t < HALF4)
            x1f[(1 - r) * HALF4 + t] = peer_x1[t];
        cluster.sync();                         // protect x1mine reuse
    }

    // ---- Steady state: it-th iteration does p2(s) fused with p1(s+64)
    for (int it = 0; it < SPP; ++it) {
        const int  s        = q + it * NPAIR;
        const bool has_next = (it + 1 < SPP);
        const int  snext    = s + NPAIR;

        if (has_next && t < NT4)
            xs[t] = x4[(size_t)snext * NT4 + t];
        __syncthreads();   // xs/x1f ready; partA/partB free

        const float4* __restrict__ apc =
            A4 + ((size_t)s * Nn + j0) * NT4 + r * HALF4;
        float4 b0 = zero4();

        if (has_next) {
            const float4* __restrict__ apn =
                A4 + ((size_t)snext * Nn + j0) * NT4 + r * HALF4;
            float4 a0 = zero4();
#pragma unroll 2
            for (int jj = 0; jj < JPG; ++jj) {
                float4 c  = __ldlu(&apc[(size_t)jj * NT4 + ti]);  // p2: L2, last-use
                float4 n  = apn[(size_t)jj * NT4 + ti];           // p1: HBM, fill L2
                float4 v1 = x1f[(j0 + jj) * 3 + lq];
                float4 v0 = xs[(j0 + jj) * 3 + lq];
                fma4(b0, c, v1);
                fma4(a0, n, v0);
            }
            partA[g][ti] = a0;
        } else {
#pragma unroll 4
            for (int jj = 0; jj < JPG; ++jj) {
                float4 c  = __ldlu(&apc[(size_t)jj * NT4 + ti]);
                fma4(b0, c, x1f[(j0 + jj) * 3 + lq]);
            }
        }
        partB[g][ti] = b0;
        __syncthreads();   // partials ready; fused loop done with x1f

        if (t < HALF4) {
            float4 r2 = add4(add4(partB[0][t], partB[1][t]),
                             add4(partB[2][t], partB[3][t]));
            const int b = s / Cn;
            const int i = s % Cn;
            // h[b, i, half r] = x1 half ; h[b, C+i, half r] = x2 half
            ((float4*)(g_h + ((size_t)b * 2 * Cn + i) * NT))[r * HALF4 + t] =
                x1f[r * HALF4 + t];
            ((float4*)(g_h + ((size_t)b * 2 * Cn + Cn + i) * NT))[r * HALF4 + t] = r2;
            if (has_next) {
                float4 r1n = add4(add4(partA[0][t], partA[1][t]),
                                  add4(partA[2][t], partA[3][t]));
                x1mine[t]          = r1n;
                x1f[r * HALF4 + t] = r1n;
            }
        }
        if (has_next) {
            cluster.sync();                      // publish x1mine
            if (t < HALF4)
                x1f[(1 - r) * HALF4 + t] = peer_x1[t];
            cluster.sync();                      // protect x1mine reuse
        }
    }
}

// ---------------------------------------------------------------------------
// Kernel 2: 1x1 conv channel mix, smem-tiled GEMM (R3 version, 10.6us).
// Block: 256 threads, tile = 64 outs x 64 cols. Thread computes 4 outs x 4 cols.
// ---------------------------------------------------------------------------
#define MIX_COLS 64
#define MIX_NCB  (NT / MIX_COLS)   // 24

__global__ __launch_bounds__(256) void mix_kernel(const float* __restrict__ W,
                                                  const float* __restrict__ bias,
                                                  float* __restrict__ out) {
    __shared__ float4 hs[(2 * Cn) * (MIX_COLS / 4)];   // 16 KB
    __shared__ float  Ws[COn * 2 * Cn];                // 16 KB
    __shared__ float  bs[COn];

    const int t    = threadIdx.x;
    const int b    = blockIdx.x / MIX_NCB;
    const int col0 = (blockIdx.x % MIX_NCB) * MIX_COLS;
    const int colq = t & 15;
    const int oq   = t >> 4;

    {
        float4*       Wd = (float4*)Ws;
        const float4* W4 = (const float4*)W;
#pragma unroll
        for (int s = 0; s < 4; ++s) Wd[t + 256 * s] = W4[t + 256 * s];
        if (t < COn) bs[t] = bias[t];
    }
    {
        const float* hb = g_h + (size_t)b * 2 * Cn * NT + col0;
#pragma unroll
        for (int s = 0; s < 4; ++s) {
            int idx = t + 256 * s;
            int c   = idx >> 4;
            int v   = idx & 15;
            hs[idx] = ((const float4*)(hb + (size_t)c * NT))[v];
        }
    }
    __syncthreads();

    float4 acc0 = make_float4(bs[4 * oq + 0], bs[4 * oq + 0], bs[4 * oq + 0], bs[4 * oq + 0]);
    float4 acc1 = make_float4(bs[4 * oq + 1], bs[4 * oq + 1], bs[4 * oq + 1], bs[4 * oq + 1]);
    float4 acc2 = make_float4(bs[4 * oq + 2], bs[4 * oq + 2], bs[4 * oq + 2], bs[4 * oq + 2]);
    float4 acc3 = make_float4(bs[4 * oq + 3], bs[4 * oq + 3], bs[4 * oq + 3], bs[4 * oq + 3]);

#pragma unroll 8
    for (int c = 0; c < 2 * Cn; ++c) {
        float4 hv = hs[c * 16 + colq];
        float  w0 = Ws[(4 * oq + 0) * 2 * Cn + c];
        float  w1 = Ws[(4 * oq + 1) * 2 * Cn + c];
        float  w2 = Ws[(4 * oq + 2) * 2 * Cn + c];
        float  w3 = Ws[(4 * oq + 3) * 2 * Cn + c];
        acc0.x = fmaf(w0, hv.x, acc0.x); acc0.y = fmaf(w0, hv.y, acc0.y);
        acc0.z = fmaf(w0, hv.z, acc0.z); acc0.w = fmaf(w0, hv.w, acc0.w);
        acc1.x = fmaf(w1, hv.x, acc1.x); acc1.y = fmaf(w1, hv.y, acc1.y);
        acc1.z = fmaf(w1, hv.z, acc1.z); acc1.w = fmaf(w1, hv.w, acc1.w);
        acc2.x = fmaf(w2, hv.x, acc2.x); acc2.y = fmaf(w2, hv.y, acc2.y);
        acc2.z = fmaf(w2, hv.z, acc2.z); acc2.w = fmaf(w2, hv.w, acc2.w);
        acc3.x = fmaf(w3, hv.x, acc3.x); acc3.y = fmaf(w3, hv.y, acc3.y);
        acc3.z = fmaf(w3, hv.z, acc3.z); acc3.w = fmaf(w3, hv.w, acc3.w);
    }

    float* ob = out + (size_t)b * COn * NT + col0;
    ((float4*)(ob + (size_t)(4 * oq + 0) * NT))[colq] = acc0;
    ((float4*)(ob + (size_t)(4 * oq + 1) * NT))[colq] = acc1;
    ((float4*)(ob + (size_t)(4 * oq + 2) * NT))[colq] = acc2;
    ((float4*)(ob + (size_t)(4 * oq + 3) * NT))[colq] = acc3;
}

// ---------------------------------------------------------------------------
extern "C" void kernel_launch(void* const* d_in, const int* in_sizes, int n_in,
                              void* d_out, int out_size) {
    const float* x    = (const float*)d_in[0];   // [B,C,N,T]
    const float* A    = (const float*)d_in[1];   // [B,C,N,N,T]
    const float* W    = (const float*)d_in[2];   // [C_OUT, 2C]
    const float* bias = (const float*)d_in[3];   // [C_OUT]
    float* out = (float*)d_out;                  // [B,C_OUT,N,T]

    cudaFuncSetAttribute(prop_kernel, cudaFuncAttributeMaxDynamicSharedMemorySize, PROP_PAD);

    prop_kernel<<<PROP_CTAS, PROP_THREADS, PROP_PAD>>>(x, A);
    mix_kernel<<<Bn * MIX_NCB, 256>>>(W, bias, out);
}

// round 6
// speedup vs baseline: 1.4284x; 1.1533x over previous
#include <cuda_runtime.h>

// Problem constants
#define Bn  16
#define Cn  32
#define Nn  128
#define Tn  12
#define COn 64
#define NT  (Nn * Tn)          // 1536 floats per (b,i,j) row of A
#define NT4 (NT / 4)           // 384 float4
#define NSLICE (Bn * Cn)       // 512 (b,i) slices

// prop config: 128 persistent CTAs (1/SM via smem pad), 768 threads =
// 4 groups x 192; each group streams 32 of the 128 j-rows.
#define PROP_CTAS    128
#define PROP_THREADS 768
#define NGRP 4
#define GSZ  192
#define JPG  (Nn / NGRP)       // 32
#define PROP_PAD (150 * 1024)  // dummy dynamic smem -> 1 CTA/SM

// Scratch: h = concat([x1, x2], channel axis) -> [B][2C][N*T] = 6.3 MB
__device__ float g_h[(size_t)Bn * 2 * Cn * NT];

extern __shared__ char s_pad[];   // occupancy limiter (never accessed)

__device__ __forceinline__ void fma4(float4& acc, const float4 a, const float4 v) {
    acc.x = fmaf(a.x, v.x, acc.x);
    acc.y = fmaf(a.y, v.y, acc.y);
    acc.z = fmaf(a.z, v.z, acc.z);
    acc.w = fmaf(a.w, v.w, acc.w);
}
__device__ __forceinline__ float4 add4(const float4 a, const float4 b) {
    return make_float4(a.x + b.x, a.y + b.y, a.z + b.z, a.w + b.w);
}

// ---------------------------------------------------------------------------
// Kernel 1: fused order-1 + order-2 propagation (R3 structure, proven 92us).
// Persistent, 1 CTA/SM, 24 warps. Pass 1 streams the slice from HBM (fills
// L2 + leaves the ~192KB tail in L1). Pass 2 re-reads the slice in REVERSE
// j-order with default (L1-caching) loads: the freshest rows hit L1, the
// rest hit L2. Chip-wide phase lockstep keeps the concurrent L2 footprint at
// 128 x 786KB = 100MB <= 126MB.
// ---------------------------------------------------------------------------
__global__ __launch_bounds__(PROP_THREADS, 1)
void prop_kernel(const float* __restrict__ x, const float* __restrict__ A) {
    __shared__ float4 part[NGRP][NT4];   // 24 KB partial sums
    __shared__ float4 xs[NT4];           // x slice,  [j*3 + lq]
    __shared__ float4 x1s[NT4];          // x1 slice, same layout

    const int t  = threadIdx.x;
    const int g  = t / GSZ;
    const int ti = t - g * GSZ;          // 0..191
    const int lq = ti % 3;
    const int j0 = g * JPG;

    for (int bc = blockIdx.x; bc < NSLICE; bc += PROP_CTAS) {
        const float4* __restrict__ xp = (const float4*)(x + (size_t)bc * NT);
        const float4* __restrict__ Ap = (const float4*)(A + (size_t)bc * Nn * NT);

        if (t < NT4) xs[t] = xp[t];
        __syncthreads();   // also the end-of-previous-iteration barrier

        // ---- Pass 1: x1[k,l] = sum_j x[j,l] * A[j,k,l]  (HBM stream)
        float4 acc0 = make_float4(0.f, 0.f, 0.f, 0.f);
        float4 acc1 = make_float4(0.f, 0.f, 0.f, 0.f);
        {
            const float4* __restrict__ ap = Ap + (size_t)j0 * NT4;
#pragma unroll 4
            for (int jj = 0; jj < JPG; ++jj) {
                float4 a0 = ap[jj * NT4 + ti];
                float4 a1 = ap[jj * NT4 + ti + GSZ];
                float4 xv = xs[(j0 + jj) * 3 + lq];
                fma4(acc0, a0, xv);
                fma4(acc1, a1, xv);
            }
        }
        part[g][ti]       = acc0;
        part[g][ti + GSZ] = acc1;
        __syncthreads();

        // ---- Reduce 1: x1 = sum of 4 partials
        float4 r1;
        if (t < NT4) {
            r1 = add4(add4(part[0][t], part[1][t]), add4(part[2][t], part[3][t]));
            x1s[t] = r1;
        }
        __syncthreads();

        // ---- Pass 2: reversed j-order -> freshest rows hit L1, rest L2
        acc0 = make_float4(0.f, 0.f, 0.f, 0.f);
        acc1 = make_float4(0.f, 0.f, 0.f, 0.f);
        {
            const float4* __restrict__ ap = Ap + (size_t)j0 * NT4;
#pragma unroll 4
            for (int jj = JPG - 1; jj >= 0; --jj) {
                float4 a0 = ap[jj * NT4 + ti];
                float4 a1 = ap[jj * NT4 + ti + GSZ];
                float4 xv = x1s[(j0 + jj) * 3 + lq];
                fma4(acc0, a0, xv);
                fma4(acc1, a1, xv);
            }
        }
        part[g][ti]       = acc0;
        part[g][ti + GSZ] = acc1;
        __syncthreads();

        // ---- Reduce 2 + write h[b,i,:] = x1, h[b,C+i,:] = x2
        if (t < NT4) {
            float4 r2 = add4(add4(part[0][t], part[1][t]), add4(part[2][t], part[3][t]));
            const int b = bc / Cn;
            const int i = bc % Cn;
            ((float4*)(g_h + ((size_t)b * 2 * Cn + i) * NT))[t]      = r1;
            ((float4*)(g_h + ((size_t)b * 2 * Cn + Cn + i) * NT))[t] = r2;
        }
    }
}

// ---------------------------------------------------------------------------
// Kernel 2: 1x1 conv channel mix, PERSISTENT smem GEMM.
// 128 blocks x 256 threads; each block owns exactly 3 of the 384
// (batch, 64-col) tiles, loads W/bias ONCE, and double-buffers the h tile
// through registers so tile k+1's global loads overlap tile k's FMA loop.
// Thread (oq=t/16, colq=t%16) computes 4 outs x 4 cols.
// ---------------------------------------------------------------------------
#define MIX_COLS 64
#define MIX_NCB  (NT / MIX_COLS)       // 24
#define MIX_TILES (Bn * MIX_NCB)       // 384
#define MIX_BLOCKS 128
#define MIX_TPB (MIX_TILES / MIX_BLOCKS)   // 3

__global__ __launch_bounds__(256) void mix_kernel(const float* __restrict__ W,
                                                  const float* __restrict__ bias,
                                                  float* __restrict__ out) {
    __shared__ float4 hs[(2 * Cn) * (MIX_COLS / 4)];   // 16 KB
    __shared__ float  Ws[COn * 2 * Cn];                // 16 KB
    __shared__ float  bs[COn];

    const int t    = threadIdx.x;
    const int colq = t & 15;
    const int oq   = t >> 4;
    const int tile0 = blockIdx.x * MIX_TPB;

    // Load W [64x64] and bias once
    {
        float4*       Wd = (float4*)Ws;
        const float4* W4 = (const float4*)W;
#pragma unroll
        for (int s = 0; s < 4; ++s) Wd[t + 256 * s] = W4[t + 256 * s];
        if (t < COn) bs[t] = bias[t];
    }

    // Prefetch first h tile into registers
    float4 pref[4];
    {
        const int b    = tile0 / MIX_NCB;
        const int col0 = (tile0 % MIX_NCB) * MIX_COLS;
        const float* hb = g_h + (size_t)b * 2 * Cn * NT + col0;
#pragma unroll
        for (int s = 0; s < 4; ++s) {
            int idx = t + 256 * s;
            int c   = idx >> 4;
            int v   = idx & 15;
            pref[s] = ((const float4*)(hb + (size_t)c * NT))[v];
        }
    }
    __syncthreads();   // Ws/bs ready

#pragma unroll
    for (int k = 0; k < MIX_TPB; ++k) {
        // publish prefetched tile
#pragma unroll
        for (int s = 0; s < 4; ++s) hs[t + 256 * s] = pref[s];
        __syncthreads();   // hs ready

        const int tile = tile0 + k;
        const int b    = tile / MIX_NCB;
        const int col0 = (tile % MIX_NCB) * MIX_COLS;

        // kick off next tile's loads (overlap with FMA loop below)
        if (k + 1 < MIX_TPB) {
            const int tn    = tile + 1;
            const int bn    = tn / MIX_NCB;
            const int col0n = (tn % MIX_NCB) * MIX_COLS;
            const float* hb = g_h + (size_t)bn * 2 * Cn * NT + col0n;
#pragma unroll
            for (int s = 0; s < 4; ++s) {
                int idx = t + 256 * s;
                int c   = idx >> 4;
                int v   = idx & 15;
                pref[s] = ((const float4*)(hb + (size_t)c * NT))[v];
            }
        }

        float4 acc0 = make_float4(bs[4 * oq + 0], bs[4 * oq + 0], bs[4 * oq + 0], bs[4 * oq + 0]);
        float4 acc1 = make_float4(bs[4 * oq + 1], bs[4 * oq + 1], bs[4 * oq + 1], bs[4 * oq + 1]);
        float4 acc2 = make_float4(bs[4 * oq + 2], bs[4 * oq + 2], bs[4 * oq + 2], bs[4 * oq + 2]);
        float4 acc3 = make_float4(bs[4 * oq + 3], bs[4 * oq + 3], bs[4 * oq + 3], bs[4 * oq + 3]);

#pragma unroll 8
        for (int c = 0; c < 2 * Cn; ++c) {
            float4 hv = hs[c * 16 + colq];
            float  w0 = Ws[(4 * oq + 0) * 2 * Cn + c];
            float  w1 = Ws[(4 * oq + 1) * 2 * Cn + c];
            float  w2 = Ws[(4 * oq + 2) * 2 * Cn + c];
            float  w3 = Ws[(4 * oq + 3) * 2 * Cn + c];
            acc0.x = fmaf(w0, hv.x, acc0.x); acc0.y = fmaf(w0, hv.y, acc0.y);
            acc0.z = fmaf(w0, hv.z, acc0.z); acc0.w = fmaf(w0, hv.w, acc0.w);
            acc1.x = fmaf(w1, hv.x, acc1.x); acc1.y = fmaf(w1, hv.y, acc1.y);
            acc1.z = fmaf(w1, hv.z, acc1.z); acc1.w = fmaf(w1, hv.w, acc1.w);
            acc2.x = fmaf(w2, hv.x, acc2.x); acc2.y = fmaf(w2, hv.y, acc2.y);
            acc2.z = fmaf(w2, hv.z, acc2.z); acc2.w = fmaf(w2, hv.w, acc2.w);
            acc3.x = fmaf(w3, hv.x, acc3.x); acc3.y = fmaf(w3, hv.y, acc3.y);
            acc3.z = fmaf(w3, hv.z, acc3.z); acc3.w = fmaf(w3, hv.w, acc3.w);
        }

        float* ob = out + (size_t)b * COn * NT + col0;
        ((float4*)(ob + (size_t)(4 * oq + 0) * NT))[colq] = acc0;
        ((float4*)(ob + (size_t)(4 * oq + 1) * NT))[colq] = acc1;
        ((float4*)(ob + (size_t)(4 * oq + 2) * NT))[colq] = acc2;
        ((float4*)(ob + (size_t)(4 * oq + 3) * NT))[colq] = acc3;

        __syncthreads();   // all reads of hs done before next publish
    }
}

// ---------------------------------------------------------------------------
extern "C" void kernel_launch(void* const* d_in, const int* in_sizes, int n_in,
                              void* d_out, int out_size) {
    const float* x    = (const float*)d_in[0];   // [B,C,N,T]
    const float* A    = (const float*)d_in[1];   // [B,C,N,N,T]
    const float* W    = (const float*)d_in[2];   // [C_OUT, 2C]
    const float* bias = (const float*)d_in[3];   // [C_OUT]
    float* out = (float*)d_out;                  // [B,C_OUT,N,T]

    cudaFuncSetAttribute(prop_kernel, cudaFuncAttributeMaxDynamicSharedMemorySize, PROP_PAD);

    prop_kernel<<<PROP_CTAS, PROP_THREADS, PROP_PAD>>>(x, A);
    mix_kernel<<<MIX_BLOCKS, 256>>>(W, bias, out);
}